// round 4
// baseline (speedup 1.0000x reference)
#include <cuda_runtime.h>
#include <cstdint>
#include <cstddef>

#define B_ 2
#define H_ 16
#define S_ 2048
#define D_ 128
#define MQ 32                        // q rows per CTA (kernel A)
#define SCALE_L2E 0.12751744912f     // (1/sqrt(128)) * log2(e)
#define L2E       1.4426950408889634f

__device__ __forceinline__ unsigned f2tf(float x){
    unsigned u; asm("cvt.rna.tf32.f32 %0, %1;" : "=r"(u) : "f"(x)); return u;
}
__device__ __forceinline__ void mma_tf32(float* c,
    unsigned a0,unsigned a1,unsigned a2,unsigned a3, unsigned b0, unsigned b1){
    asm volatile("mma.sync.aligned.m16n8k8.row.col.f32.tf32.tf32.f32 "
        "{%0,%1,%2,%3}, {%4,%5,%6,%7}, {%8,%9}, {%0,%1,%2,%3};"
        : "+f"(c[0]),"+f"(c[1]),"+f"(c[2]),"+f"(c[3])
        : "r"(a0),"r"(a1),"r"(a2),"r"(a3),"r"(b0),"r"(b1));
}
// exp2 on the FMA pipe; valid for t<=0, clamped at -126; ~4e-5 rel err
__device__ __forceinline__ float exp2_fast(float t){
    t = fmaxf(t, -126.0f);
    float r = t + 12582912.0f;
    float f = t - (r - 12582912.0f);
    float p = 0.009618129f;
    p = fmaf(p, f, 0.055504109f);
    p = fmaf(p, f, 0.240226507f);
    p = fmaf(p, f, 0.693147181f);
    p = fmaf(p, f, 1.0f);
    return __uint_as_float(__float_as_uint(p) + (__float_as_uint(r) << 23));
}

// ============================ Kernel A: scores + softmax -> attn ============================
__global__ __launch_bounds__(512,2)
void scores_kernel(const float* __restrict__ q, const float* __restrict__ k,
                   const int* __restrict__ mask, const float* __restrict__ bias,
                   float* __restrict__ attn)
{
    __shared__ float qs[MQ*132];      // permuted tf32 Q tile
    __shared__ float redP[16*32];     // per-warp row maxes
    __shared__ float redM[32];        // final row max
    __shared__ float redS[32];        // row sum -> inverse

    const int tid = threadIdx.x, warp = tid>>5, lane = tid&31;
    const int g = lane>>2, ctg = lane&3;
    const int h = blockIdx.y>>1, b = blockIdx.y&1;
    const int q0 = blockIdx.x*MQ;
    const size_t bh = (size_t)(b*H_+h);
    const float* qp = q + (bh*S_+q0)*(size_t)D_;
    const float* kp = k + bh*(size_t)S_*D_;
    float* attn_base = attn + (bh*S_+q0)*(size_t)S_;

    // ---- stage Q: permute within 8-col groups: col c -> (c&3)*2 + (c>>2) ----
    {
        int r = tid>>4, blk = tid&15;            // 512 = 32 rows x 16 groups
        const float* src = qp + r*D_ + blk*8;
        float4 t0 = *(const float4*)(src);
        float4 t1 = *(const float4*)(src+4);
        unsigned* dst = (unsigned*)(qs + r*132 + blk*8);
        dst[0]=f2tf(t0.x); dst[2]=f2tf(t0.y); dst[4]=f2tf(t0.z); dst[6]=f2tf(t0.w);
        dst[1]=f2tf(t1.x); dst[3]=f2tf(t1.y); dst[5]=f2tf(t1.z); dst[7]=f2tf(t1.w);
    }
    __syncthreads();

    // ---- phase 1: QK^T streamed; raw log2-domain scores -> attn; online row max ----
    const unsigned* q0L = (const unsigned*)(qs +  g    *132) + 2*ctg;
    const unsigned* q0H = (const unsigned*)(qs + (g+ 8)*132) + 2*ctg;
    const unsigned* q1L = (const unsigned*)(qs + (g+16)*132) + 2*ctg;
    const unsigned* q1H = (const unsigned*)(qs + (g+24)*132) + 2*ctg;
    const int colw = warp*8 + 2*ctg;
    const float* bp = bias + ((size_t)h*S_ + q0+g)*S_ + colw;
    const int*   mp = mask + ((size_t)b*S_ + q0+g)*S_ + colw;
    float*       ap = attn_base + (size_t)(g)*S_ + colw;
    const size_t r8 = 8*(size_t)S_;

    float m0=-3.4e38f, m1=-3.4e38f, m2=-3.4e38f, m3=-3.4e38f;

    #pragma unroll 1
    for (int t=0; t<16; ++t){
        const float* kpt = kp + (size_t)(t*128 + warp*8 + g)*D_ + ctg;
        float acc0[4]={0.f,0.f,0.f,0.f}, acc1[4]={0.f,0.f,0.f,0.f};
        #pragma unroll
        for (int dk=0; dk<16; ++dk){
            uint2 aL = *(const uint2*)(q0L + dk*8);
            uint2 aH = *(const uint2*)(q0H + dk*8);
            uint2 cL = *(const uint2*)(q1L + dk*8);
            uint2 cH = *(const uint2*)(q1H + dk*8);
            unsigned b0 = f2tf(__ldg(kpt + dk*8));
            unsigned b1 = f2tf(__ldg(kpt + dk*8 + 4));
            mma_tf32(acc0, aL.x, aH.x, aL.y, aH.y, b0, b1);
            mma_tf32(acc1, cL.x, cH.x, cL.y, cH.y, b0, b1);
        }
        const int co = t*128;
        // row groups: acc0[0,1]->g ; acc0[2,3]->g+8 ; acc1[0,1]->g+16 ; acc1[2,3]->g+24
        {
            float2 bb = *(const float2*)(bp + co); int2 mm = *(const int2*)(mp + co);
            float x0 = mm.x ? fmaf(bb.x, L2E, acc0[0]*SCALE_L2E) : -1e9f;
            float x1 = mm.y ? fmaf(bb.y, L2E, acc0[1]*SCALE_L2E) : -1e9f;
            m0 = fmaxf(m0, fmaxf(x0,x1));
            *(float2*)(ap + co) = make_float2(x0,x1);
        }
        {
            float2 bb = *(const float2*)(bp + r8 + co); int2 mm = *(const int2*)(mp + r8 + co);
            float x0 = mm.x ? fmaf(bb.x, L2E, acc0[2]*SCALE_L2E) : -1e9f;
            float x1 = mm.y ? fmaf(bb.y, L2E, acc0[3]*SCALE_L2E) : -1e9f;
            m1 = fmaxf(m1, fmaxf(x0,x1));
            *(float2*)(ap + r8 + co) = make_float2(x0,x1);
        }
        {
            float2 bb = *(const float2*)(bp + 2*r8 + co); int2 mm = *(const int2*)(mp + 2*r8 + co);
            float x0 = mm.x ? fmaf(bb.x, L2E, acc1[0]*SCALE_L2E) : -1e9f;
            float x1 = mm.y ? fmaf(bb.y, L2E, acc1[1]*SCALE_L2E) : -1e9f;
            m2 = fmaxf(m2, fmaxf(x0,x1));
            *(float2*)(ap + 2*r8 + co) = make_float2(x0,x1);
        }
        {
            float2 bb = *(const float2*)(bp + 3*r8 + co); int2 mm = *(const int2*)(mp + 3*r8 + co);
            float x0 = mm.x ? fmaf(bb.x, L2E, acc1[2]*SCALE_L2E) : -1e9f;
            float x1 = mm.y ? fmaf(bb.y, L2E, acc1[3]*SCALE_L2E) : -1e9f;
            m3 = fmaxf(m3, fmaxf(x0,x1));
            *(float2*)(ap + 3*r8 + co) = make_float2(x0,x1);
        }
    }

    // ---- cross-lane/warp max reduce ----
    m0 = fmaxf(m0, __shfl_xor_sync(~0u,m0,1)); m0 = fmaxf(m0, __shfl_xor_sync(~0u,m0,2));
    m1 = fmaxf(m1, __shfl_xor_sync(~0u,m1,1)); m1 = fmaxf(m1, __shfl_xor_sync(~0u,m1,2));
    m2 = fmaxf(m2, __shfl_xor_sync(~0u,m2,1)); m2 = fmaxf(m2, __shfl_xor_sync(~0u,m2,2));
    m3 = fmaxf(m3, __shfl_xor_sync(~0u,m3,1)); m3 = fmaxf(m3, __shfl_xor_sync(~0u,m3,2));
    if (ctg==0){
        redP[warp*32 + g     ] = m0;
        redP[warp*32 + g +  8] = m1;
        redP[warp*32 + g + 16] = m2;
        redP[warp*32 + g + 24] = m3;
    }
    __threadfence_block();
    __syncthreads();
    if (tid<32){
        float mm=-3.4e38f;
        #pragma unroll
        for (int w=0; w<16; ++w) mm = fmaxf(mm, redP[w*32+tid]);
        redM[tid]=mm;
    }
    __syncthreads();

    // ---- phase 2a: p = exp2(x - m), rowsum; warp w owns rows 2w, 2w+1 ----
    #pragma unroll
    for (int rr=0; rr<2; ++rr){
        int row = warp*2 + rr;
        float mrow = redM[row];
        float* rp = attn_base + (size_t)row*S_ + lane*4;
        float s = 0.f;
        #pragma unroll
        for (int i=0;i<16;++i){
            float4 x = *(const float4*)(rp + i*128);
            float4 p;
            p.x = exp2_fast(x.x - mrow); p.y = exp2_fast(x.y - mrow);
            p.z = exp2_fast(x.z - mrow); p.w = exp2_fast(x.w - mrow);
            *(float4*)(rp + i*128) = p;
            s += (p.x+p.y)+(p.z+p.w);
        }
        #pragma unroll
        for (int o=16;o;o>>=1) s += __shfl_xor_sync(~0u, s, o);
        if (lane==0) redS[row]=s;
    }
    __syncthreads();
    if (tid<32) redS[tid] = 1.0f/redS[tid];
    __syncthreads();

    // ---- phase 2b: normalize in place ----
    #pragma unroll
    for (int rr=0; rr<2; ++rr){
        int row = warp*2 + rr;
        float inv = redS[row];
        float* rp = attn_base + (size_t)row*S_ + lane*4;
        #pragma unroll
        for (int i=0;i<16;++i){
            float4 p = *(const float4*)(rp + i*128);
            p.x*=inv; p.y*=inv; p.z*=inv; p.w*=inv;
            *(float4*)(rp + i*128) = p;
        }
    }
}

// ============================ Kernel B: out = attn @ V ============================
__global__ __launch_bounds__(1024,1)
void pv_kernel(const float* __restrict__ attn, const float* __restrict__ v,
               float* __restrict__ out)
{
    const int tid = threadIdx.x, wid = tid>>5, lane = tid&31;
    const int g = lane>>2, ctg = lane&3;
    const int mblk = wid>>2, nw = wid&3;
    const size_t bh = blockIdx.y;
    const int m0 = blockIdx.x*128 + mblk*16;
    const int n0 = nw*32;

    const float* aL = attn + (bh*S_ + m0 + g    )*(size_t)S_ + ctg;
    const float* aH = attn + (bh*S_ + m0 + g + 8)*(size_t)S_ + ctg;
    const float* vb = v + bh*(size_t)S_*D_ + (size_t)ctg*D_ + n0 + g;

    float acc[4][4] = {};
    #pragma unroll 4
    for (int ks=0; ks<256; ++ks){
        const int kb = ks*8;
        unsigned a0 = f2tf(__ldg(aL + kb));
        unsigned a1 = f2tf(__ldg(aH + kb));
        unsigned a2 = f2tf(__ldg(aL + kb + 4));
        unsigned a3 = f2tf(__ldg(aH + kb + 4));
        const float* vk = vb + (size_t)kb*D_;
        #pragma unroll
        for (int j=0;j<4;++j){
            unsigned b0 = f2tf(__ldg(vk + j*8));
            unsigned b1 = f2tf(__ldg(vk + 4*D_ + j*8));
            mma_tf32(acc[j], a0,a1,a2,a3, b0,b1);
        }
    }

    float* opL = out + (bh*S_ + m0 + g    )*(size_t)D_ + n0 + 2*ctg;
    float* opH = out + (bh*S_ + m0 + g + 8)*(size_t)D_ + n0 + 2*ctg;
    #pragma unroll
    for (int j=0;j<4;++j){
        *(float2*)(opL + j*8) = make_float2(acc[j][0], acc[j][1]);
        *(float2*)(opH + j*8) = make_float2(acc[j][2], acc[j][3]);
    }
}

extern "C" void kernel_launch(void* const* d_in, const int* in_sizes, int n_in,
                              void* d_out, int out_size)
{
    const float* q    = (const float*)d_in[0];
    const float* k    = (const float*)d_in[1];
    const float* v    = (const float*)d_in[2];
    const int*   mask = (const int*)  d_in[3];
    const float* bias = (const float*)d_in[4];
    float* out  = (float*)d_out;
    float* attn = out + (size_t)B_*H_*S_*D_;   // tuple output: (out, attn)

    dim3 gA(S_/MQ, 2*H_);          // x = q-tile (consecutive bids share (b,h) -> K L2-hot)
    scores_kernel<<<gA, 512>>>(q, k, mask, bias, attn);

    dim3 gB(S_/128, B_*H_);        // x = m-tile, y = bh
    pv_kernel<<<gB, 1024>>>(attn, v, out);
}

// round 8
// speedup vs baseline: 1.7984x; 1.7984x over previous
#include <cuda_runtime.h>
#include <cstdint>
#include <cstddef>

#define B_ 2
#define H_ 16
#define S_ 2048
#define D_ 128
#define SCALE_L2E 0.12751744912f     // (1/sqrt(128)) * log2(e)
#define L2E       1.4426950408889634f

__device__ __forceinline__ unsigned f2tf(float x){
    unsigned u; asm("cvt.rna.tf32.f32 %0, %1;" : "=r"(u) : "f"(x)); return u;
}
__device__ __forceinline__ void mma_tf32(float* c,
    unsigned a0,unsigned a1,unsigned a2,unsigned a3, unsigned b0, unsigned b1){
    asm volatile("mma.sync.aligned.m16n8k8.row.col.f32.tf32.tf32.f32 "
        "{%0,%1,%2,%3}, {%4,%5,%6,%7}, {%8,%9}, {%0,%1,%2,%3};"
        : "+f"(c[0]),"+f"(c[1]),"+f"(c[2]),"+f"(c[3])
        : "r"(a0),"r"(a1),"r"(a2),"r"(a3),"r"(b0),"r"(b1));
}
__device__ __forceinline__ void cpa16(float* dst, const float* src){
    unsigned d = (unsigned)__cvta_generic_to_shared(dst);
    asm volatile("cp.async.cg.shared.global [%0], [%1], 16;" :: "r"(d), "l"(src));
}
#define CP_COMMIT() asm volatile("cp.async.commit_group;")
#define CP_WAIT0()  asm volatile("cp.async.wait_group 0;")

// exp2 on the FMA pipe; clamped at -126; ~4e-5 rel err
__device__ __forceinline__ float exp2_fast(float t){
    t = fmaxf(t, -126.0f);
    float r = t + 12582912.0f;
    float f = t - (r - 12582912.0f);
    float p = 0.009618129f;
    p = fmaf(p, f, 0.055504109f);
    p = fmaf(p, f, 0.240226507f);
    p = fmaf(p, f, 0.693147181f);
    p = fmaf(p, f, 1.0f);
    return __uint_as_float(__float_as_uint(p) + (__float_as_uint(r) << 23));
}

// ===================== Kernel A: e = exp2(masked scores), then normalize =====================
#define PQ 132
#define PK 132
#define QS_FLOATS (128*PQ)                       // 16896
#define KT_FLOATS (128*PK)                       // 16896
#define A_SMEM_FLOATS (QS_FLOATS + 2*KT_FLOATS + 768)
#define A_SMEM_BYTES  (A_SMEM_FLOATS*4)          // 205824

// 128 rows x 128 floats = 128 rows x 32 16B-segments = 4096 transfers = 8 x 512 threads
__device__ __forceinline__ void load_kchunk(float* dst, const float* src, int tid){
    #pragma unroll
    for (int i=0;i<8;i++){
        int c = tid + i*512;
        int row = c>>5, c16 = c&31;              // FIXED: was c>>3 / c&7 (smem OOB)
        cpa16(dst + row*PK + c16*4, src + (size_t)row*D_ + c16*4);
    }
}

__global__ __launch_bounds__(512,1)
void scores_kernel(const float* __restrict__ q, const float* __restrict__ k,
                   const int* __restrict__ mask, const float* __restrict__ bias,
                   float* __restrict__ attn)
{
    extern __shared__ float smem[];
    float* qs   = smem;
    float* kbuf = smem + QS_FLOATS;
    float* red  = smem + QS_FLOATS + 2*KT_FLOATS;

    const int tid = threadIdx.x, warp = tid>>5, lane = tid&31;
    const int g = lane>>2, ctg = lane&3;
    const int wm = warp&3, wn = warp>>2;
    const int h = blockIdx.y>>1, b = blockIdx.y&1;
    const size_t bh = (size_t)(b*H_+h);
    const int m0 = blockIdx.x*128;
    const float* qp = q + (bh*S_+m0)*(size_t)D_;
    const float* kp = k + bh*(size_t)S_*D_;
    float* attn_base = attn + (bh*S_+m0)*(size_t)S_;

    // ---- stage Q as permuted tf32: within 8-group, col c -> (c&3)*2 + (c>>2) ----
    {
        int row = tid>>2, seg = tid&3;
        #pragma unroll
        for (int gi=0; gi<4; ++gi){
            int c0 = seg*32 + gi*8;
            const float* s = qp + (size_t)row*D_ + c0;
            float4 t0 = *(const float4*)(s);
            float4 t1 = *(const float4*)(s+4);
            unsigned* d = (unsigned*)(qs + row*PQ + c0);
            d[0]=f2tf(t0.x); d[2]=f2tf(t0.y); d[4]=f2tf(t0.z); d[6]=f2tf(t0.w);
            d[1]=f2tf(t1.x); d[3]=f2tf(t1.y); d[5]=f2tf(t1.z); d[7]=f2tf(t1.w);
        }
    }
    load_kchunk(kbuf, kp, tid);
    CP_COMMIT();
    __syncthreads();

    float sums[4] = {0.f,0.f,0.f,0.f};

    #pragma unroll 1
    for (int nc=0; nc<16; ++nc){
        CP_WAIT0();
        __syncthreads();
        if (nc<15){
            load_kchunk(kbuf + ((nc+1)&1)*KT_FLOATS, kp + (size_t)(nc+1)*128*D_, tid);
            CP_COMMIT();
        }
        const float* kb = kbuf + (nc&1)*KT_FLOATS;
        float acc[2][4][4] = {};
        const unsigned* qa = (const unsigned*)(qs + (wm*32+g)*PQ) + 2*ctg;
        const float* kr = kb + (wn*32+g)*PK + ctg;
        #pragma unroll
        for (int k8=0; k8<16; ++k8){
            uint2 aL0 = *(const uint2*)(qa + k8*8);
            uint2 aH0 = *(const uint2*)(qa +  8*PQ + k8*8);
            uint2 aL1 = *(const uint2*)(qa + 16*PQ + k8*8);
            uint2 aH1 = *(const uint2*)(qa + 24*PQ + k8*8);
            #pragma unroll
            for (int j=0;j<4;++j){
                unsigned b0 = f2tf(kr[j*8*PK + k8*8]);
                unsigned b1 = f2tf(kr[j*8*PK + k8*8 + 4]);
                mma_tf32(acc[0][j], aL0.x,aH0.x,aL0.y,aH0.y, b0,b1);
                mma_tf32(acc[1][j], aL1.x,aH1.x,aL1.y,aH1.y, b0,b1);
            }
        }
        // ---- epilogue: bias+mask -> e = exp2 -> attn (unnormalized), row-sum in regs ----
        const int ncol = nc*128 + wn*32 + 2*ctg;
        #pragma unroll
        for (int mi=0; mi<2; ++mi){
            #pragma unroll
            for (int hi=0; hi<2; ++hi){
                int r = wm*32 + mi*16 + hi*8 + g;
                const float* bp = bias + ((size_t)h*S_ + m0 + r)*S_ + ncol;
                const int*   mp = mask + ((size_t)b*S_ + m0 + r)*S_ + ncol;
                float* ap = attn_base + (size_t)r*S_ + ncol;
                float s = 0.f;
                #pragma unroll
                for (int j=0;j<4;++j){
                    float2 bb = *(const float2*)(bp + j*8);
                    int2   mm = *(const int2*)(mp + j*8);
                    float c0 = acc[mi][j][hi*2], c1 = acc[mi][j][hi*2+1];
                    float x0 = mm.x ? fmaf(bb.x, L2E, c0*SCALE_L2E) : -126.0f;
                    float x1 = mm.y ? fmaf(bb.y, L2E, c1*SCALE_L2E) : -126.0f;
                    float e0 = exp2_fast(x0), e1 = exp2_fast(x1);
                    *(float2*)(ap + j*8) = make_float2(e0,e1);
                    s += e0+e1;
                }
                sums[mi*2+hi] += s;
            }
        }
    }

    // ---- row-sum reduce: lanes (xor over ctg), then 4 wn warps via smem ----
    #pragma unroll
    for (int i=0;i<4;++i){
        sums[i] += __shfl_xor_sync(~0u, sums[i], 1);
        sums[i] += __shfl_xor_sync(~0u, sums[i], 2);
    }
    if (ctg==0){
        #pragma unroll
        for (int mi=0; mi<2; ++mi)
            #pragma unroll
            for (int hi=0; hi<2; ++hi)
                red[wn*128 + wm*32 + mi*16 + hi*8 + g] = sums[mi*2+hi];
    }
    __syncthreads();
    float* redS = red + 512;
    if (tid < 128){
        float s = red[tid] + red[128+tid] + red[256+tid] + red[384+tid];
        redS[tid] = 1.0f/s;
    }
    __syncthreads();

    // ---- normalize pass (CTA's own 128x2048, L2-hot) ----
    float4* ab4 = (float4*)attn_base;
    #pragma unroll 8
    for (int i=0;i<128;++i){
        int f = tid + i*512;
        float inv = redS[f>>9];
        float4 p = ab4[f];
        p.x*=inv; p.y*=inv; p.z*=inv; p.w*=inv;
        ab4[f] = p;
    }
}

// ===================== Kernel B: out = attn @ V =====================
#define PA 36
#define PB 136
#define SA_FLOATS (128*PA)               // 4608
#define SB_FLOATS (32*PB)                // 4352
#define B_STAGE   (SA_FLOATS + SB_FLOATS)
#define B_SMEM_BYTES (2*B_STAGE*4)       // 71680

__device__ __forceinline__ void load_stageB(float* sa, const float* ap, const float* vp,
                                            int ks, int tid){
    float* sb = sa + SA_FLOATS;
    // A tile: 128 rows x 32 floats = 128 x 8 segs = 1024 = 4 x 256
    #pragma unroll
    for (int i=0;i<4;++i){
        int c = tid + i*256;
        int row = c>>3, c16 = c&7;
        cpa16(sa + row*PA + c16*4, ap + (size_t)row*S_ + ks*32 + c16*4);
    }
    // V tile: 32 rows x 128 floats = 32 x 32 segs = 1024 = 4 x 256
    #pragma unroll
    for (int i=0;i<4;++i){
        int c = tid + i*256;
        int row = c>>5, c32 = c&31;
        cpa16(sb + row*PB + c32*4, vp + (size_t)(ks*32+row)*D_ + c32*4);
    }
}

__global__ __launch_bounds__(256,2)
void pv_kernel(const float* __restrict__ attn, const float* __restrict__ v,
               float* __restrict__ out)
{
    extern __shared__ float smemB[];
    const int tid = threadIdx.x, wid = tid>>5, lane = tid&31;
    const int g = lane>>2, ctg = lane&3;
    const int wm = wid&3, wn = wid>>2;
    const size_t bh = blockIdx.y;
    const int m0 = blockIdx.x*128;
    const float* ap = attn + (bh*S_+m0)*(size_t)S_;
    const float* vp = v + bh*(size_t)S_*D_;

    load_stageB(smemB, ap, vp, 0, tid);
    CP_COMMIT();

    float acc[2][8][4] = {};
    #pragma unroll 1
    for (int ks=0; ks<64; ++ks){
        CP_WAIT0();
        __syncthreads();
        if (ks<63){
            load_stageB(smemB + ((ks+1)&1)*B_STAGE, ap, vp, ks+1, tid);
            CP_COMMIT();
        }
        const float* sa = smemB + (ks&1)*B_STAGE;
        const float* sb = sa + SA_FLOATS;
        const float* ar = sa + (wm*32+g)*PA + ctg;
        #pragma unroll
        for (int k8=0; k8<4; ++k8){
            unsigned a00 = f2tf(ar[k8*8        ]);
            unsigned a01 = f2tf(ar[k8*8 +  8*PA]);
            unsigned a02 = f2tf(ar[k8*8 + 4      ]);
            unsigned a03 = f2tf(ar[k8*8 + 4 + 8*PA]);
            unsigned a10 = f2tf(ar[k8*8 + 16*PA]);
            unsigned a11 = f2tf(ar[k8*8 + 24*PA]);
            unsigned a12 = f2tf(ar[k8*8 + 4 + 16*PA]);
            unsigned a13 = f2tf(ar[k8*8 + 4 + 24*PA]);
            const float* vr  = sb + (k8*8+ctg)*PB + wn*64 + g;
            const float* vr4 = vr + 4*PB;
            #pragma unroll
            for (int j=0;j<8;++j){
                unsigned b0 = f2tf(vr[j*8]);
                unsigned b1 = f2tf(vr4[j*8]);
                mma_tf32(acc[0][j], a00,a01,a02,a03, b0,b1);
                mma_tf32(acc[1][j], a10,a11,a12,a13, b0,b1);
            }
        }
    }

    #pragma unroll
    for (int mi=0; mi<2; ++mi){
        float* opL = out + (bh*S_ + m0 + wm*32 + mi*16 + g    )*(size_t)D_ + wn*64 + 2*ctg;
        float* opH = out + (bh*S_ + m0 + wm*32 + mi*16 + g + 8)*(size_t)D_ + wn*64 + 2*ctg;
        #pragma unroll
        for (int j=0;j<8;++j){
            *(float2*)(opL + j*8) = make_float2(acc[mi][j][0], acc[mi][j][1]);
            *(float2*)(opH + j*8) = make_float2(acc[mi][j][2], acc[mi][j][3]);
        }
    }
}

extern "C" void kernel_launch(void* const* d_in, const int* in_sizes, int n_in,
                              void* d_out, int out_size)
{
    const float* q    = (const float*)d_in[0];
    const float* k    = (const float*)d_in[1];
    const float* v    = (const float*)d_in[2];
    const int*   mask = (const int*)  d_in[3];
    const float* bias = (const float*)d_in[4];
    float* out  = (float*)d_out;
    float* attn = out + (size_t)B_*H_*S_*D_;   // tuple output: (out, attn)

    cudaFuncSetAttribute(scores_kernel,
                         cudaFuncAttributeMaxDynamicSharedMemorySize, A_SMEM_BYTES);
    cudaFuncSetAttribute(pv_kernel,
                         cudaFuncAttributeMaxDynamicSharedMemorySize, B_SMEM_BYTES);

    dim3 gA(S_/128, 2*H_);
    scores_kernel<<<gA, 512, A_SMEM_BYTES>>>(q, k, mask, bias, attn);

    dim3 gB(S_/128, B_*H_);
    pv_kernel<<<gB, 256, B_SMEM_BYTES>>>(attn, v, out);
}

// round 11
// speedup vs baseline: 2.5077x; 1.3944x over previous
#include <cuda_runtime.h>
#include <cstdint>
#include <cstddef>

#define B_ 2
#define H_ 16
#define S_ 2048
#define D_ 128
#define SCALE_L2E 0.12751744912f     // (1/sqrt(128)) * log2(e)
#define L2E       1.4426950408889634f

__device__ __forceinline__ unsigned f2tf(float x){
    unsigned u; asm("cvt.rna.tf32.f32 %0, %1;" : "=r"(u) : "f"(x)); return u;
}
__device__ __forceinline__ void mma_tf32(float* c,
    unsigned a0,unsigned a1,unsigned a2,unsigned a3, unsigned b0, unsigned b1){
    asm volatile("mma.sync.aligned.m16n8k8.row.col.f32.tf32.tf32.f32 "
        "{%0,%1,%2,%3}, {%4,%5,%6,%7}, {%8,%9}, {%0,%1,%2,%3};"
        : "+f"(c[0]),"+f"(c[1]),"+f"(c[2]),"+f"(c[3])
        : "r"(a0),"r"(a1),"r"(a2),"r"(a3),"r"(b0),"r"(b1));
}
__device__ __forceinline__ void cpa16(float* dst, const float* src){
    unsigned d = (unsigned)__cvta_generic_to_shared(dst);
    asm volatile("cp.async.cg.shared.global [%0], [%1], 16;" :: "r"(d), "l"(src));
}
#define CP_COMMIT() asm volatile("cp.async.commit_group;")
#define CP_WAIT0()  asm volatile("cp.async.wait_group 0;")

// exp2 on the FMA pipe; clamped at -126; ~4e-5 rel err
__device__ __forceinline__ float exp2_fast(float t){
    t = fmaxf(t, -126.0f);
    float r = t + 12582912.0f;
    float f = t - (r - 12582912.0f);
    float p = 0.009618129f;
    p = fmaf(p, f, 0.055504109f);
    p = fmaf(p, f, 0.240226507f);
    p = fmaf(p, f, 0.693147181f);
    p = fmaf(p, f, 1.0f);
    return __uint_as_float(__float_as_uint(p) + (__float_as_uint(r) << 23));
}

// ===================== Kernel A: e = exp2(masked scores), then normalize =====================
// m=64 q-rows per CTA, 64-key chunks, 2 CTAs/SM (32 warps) for epilogue/mma overlap.
#define MQ 64
#define KC 64
#define NC (S_/KC)                       // 32
#define PQ 132
#define PK 132
#define QS_FLOATS (MQ*PQ)                // 8448
#define KT_FLOATS (KC*PK)                // 8448
#define A_SMEM_FLOATS (QS_FLOATS + 2*KT_FLOATS + 384)   // 25728
#define A_SMEM_BYTES  (A_SMEM_FLOATS*4)                  // 102912

// 64 rows x 128 floats = 64 x 32 16B-segments = 2048 transfers = 4 x 512 threads
__device__ __forceinline__ void load_kchunk(float* dst, const float* src, int tid){
    #pragma unroll
    for (int i=0;i<4;i++){
        int c = tid + i*512;
        int row = c>>5, seg = c&31;
        cpa16(dst + row*PK + seg*4, src + (size_t)row*D_ + seg*4);
    }
}

__global__ __launch_bounds__(512,2)
void scores_kernel(const float* __restrict__ q, const float* __restrict__ k,
                   const int* __restrict__ mask, const float* __restrict__ bias,
                   float* __restrict__ attn)
{
    extern __shared__ float smem[];
    float* qs   = smem;
    float* kbuf = smem + QS_FLOATS;
    float* red  = smem + QS_FLOATS + 2*KT_FLOATS;

    const int tid = threadIdx.x, warp = tid>>5, lane = tid&31;
    const int g = lane>>2, ctg = lane&3;
    const int wm = warp&3, wn = warp>>2;     // warp tile: m16 (wm), n16 (wn)
    const int h = blockIdx.y>>1, b = blockIdx.y&1;
    const size_t bh = (size_t)(b*H_+h);
    const int m0 = blockIdx.x*MQ;
    const float* qp = q + (bh*S_+m0)*(size_t)D_;
    const float* kp = k + bh*(size_t)S_*D_;
    float* attn_base = attn + (bh*S_+m0)*(size_t)S_;

    // ---- stage Q as permuted tf32: within 8-group, col c -> (c&3)*2 + (c>>2) ----
    {
        int row = tid>>3, seg = tid&7;       // 512 thr = 64 rows x 8 segs; 2 groups each
        #pragma unroll
        for (int gi=0; gi<2; ++gi){
            int c0 = seg*16 + gi*8;
            const float* s = qp + (size_t)row*D_ + c0;
            float4 t0 = *(const float4*)(s);
            float4 t1 = *(const float4*)(s+4);
            unsigned* d = (unsigned*)(qs + row*PQ + c0);
            d[0]=f2tf(t0.x); d[2]=f2tf(t0.y); d[4]=f2tf(t0.z); d[6]=f2tf(t0.w);
            d[1]=f2tf(t1.x); d[3]=f2tf(t1.y); d[5]=f2tf(t1.z); d[7]=f2tf(t1.w);
        }
    }
    load_kchunk(kbuf, kp, tid);
    CP_COMMIT();
    __syncthreads();

    float sums[2] = {0.f,0.f};

    #pragma unroll 1
    for (int nc=0; nc<NC; ++nc){
        CP_WAIT0();
        __syncthreads();
        if (nc<NC-1){
            load_kchunk(kbuf + ((nc+1)&1)*KT_FLOATS, kp + (size_t)(nc+1)*KC*D_, tid);
            CP_COMMIT();
        }
        const float* kb = kbuf + (nc&1)*KT_FLOATS;
        float acc[2][4] = {};
        const unsigned* qa = (const unsigned*)(qs + (wm*16+g)*PQ) + 2*ctg;
        const float* kr = kb + (wn*16+g)*PK + ctg;
        #pragma unroll
        for (int k8=0; k8<16; ++k8){
            uint2 aL = *(const uint2*)(qa + k8*8);
            uint2 aH = *(const uint2*)(qa + 8*PQ + k8*8);
            #pragma unroll
            for (int j=0;j<2;++j){
                unsigned b0 = f2tf(kr[j*8*PK + k8*8]);
                unsigned b1 = f2tf(kr[j*8*PK + k8*8 + 4]);
                mma_tf32(acc[j], aL.x,aH.x,aL.y,aH.y, b0,b1);
            }
        }
        // ---- epilogue: bias+mask -> e = exp2 -> attn (unnormalized), row-sums in regs ----
        const int ncol = nc*KC + wn*16 + 2*ctg;
        #pragma unroll
        for (int hi=0; hi<2; ++hi){
            int r = wm*16 + hi*8 + g;
            const float* bp = bias + ((size_t)h*S_ + m0 + r)*S_ + ncol;
            const int*   mp = mask + ((size_t)b*S_ + m0 + r)*S_ + ncol;
            float* ap = attn_base + (size_t)r*S_ + ncol;
            float s = 0.f;
            #pragma unroll
            for (int j=0;j<2;++j){
                float2 bb = *(const float2*)(bp + j*8);
                int2   mm = *(const int2*)(mp + j*8);
                float c0 = acc[j][hi*2], c1 = acc[j][hi*2+1];
                float x0 = mm.x ? fmaf(bb.x, L2E, c0*SCALE_L2E) : -126.0f;
                float x1 = mm.y ? fmaf(bb.y, L2E, c1*SCALE_L2E) : -126.0f;
                float e0 = exp2_fast(x0), e1 = exp2_fast(x1);
                *(float2*)(ap + j*8) = make_float2(e0,e1);
                s += e0+e1;
            }
            sums[hi] += s;
        }
    }

    // ---- row-sum reduce: lanes (xor over ctg), then 4 wn groups via smem ----
    #pragma unroll
    for (int i=0;i<2;++i){
        sums[i] += __shfl_xor_sync(~0u, sums[i], 1);
        sums[i] += __shfl_xor_sync(~0u, sums[i], 2);
    }
    if (ctg==0){
        red[wn*64 + wm*16 +     g] = sums[0];
        red[wn*64 + wm*16 + 8 + g] = sums[1];
    }
    __syncthreads();
    float* redS = red + 256;
    if (tid < 64){
        float s = red[tid] + red[64+tid] + red[128+tid] + red[192+tid];
        redS[tid] = 1.0f/s;
    }
    __syncthreads();

    // ---- normalize pass (CTA's own 64x2048, L2-hot) ----
    float4* ab4 = (float4*)attn_base;
    #pragma unroll 8
    for (int i=0;i<64;++i){
        int f = tid + i*512;
        float inv = redS[f>>9];
        float4 p = ab4[f];
        p.x*=inv; p.y*=inv; p.z*=inv; p.w*=inv;
        ab4[f] = p;
    }
}

// ===================== Kernel B: out = attn @ V (unchanged from R8) =====================
#define PA 36
#define PB 136
#define SA_FLOATS (128*PA)               // 4608
#define SB_FLOATS (32*PB)                // 4352
#define B_STAGE   (SA_FLOATS + SB_FLOATS)
#define B_SMEM_BYTES (2*B_STAGE*4)       // 71680

__device__ __forceinline__ void load_stageB(float* sa, const float* ap, const float* vp,
                                            int ks, int tid){
    float* sb = sa + SA_FLOATS;
    #pragma unroll
    for (int i=0;i<4;++i){
        int c = tid + i*256;
        int row = c>>3, c16 = c&7;
        cpa16(sa + row*PA + c16*4, ap + (size_t)row*S_ + ks*32 + c16*4);
    }
    #pragma unroll
    for (int i=0;i<4;++i){
        int c = tid + i*256;
        int row = c>>5, c32 = c&31;
        cpa16(sb + row*PB + c32*4, vp + (size_t)(ks*32+row)*D_ + c32*4);
    }
}

__global__ __launch_bounds__(256,2)
void pv_kernel(const float* __restrict__ attn, const float* __restrict__ v,
               float* __restrict__ out)
{
    extern __shared__ float smemB[];
    const int tid = threadIdx.x, wid = tid>>5, lane = tid&31;
    const int g = lane>>2, ctg = lane&3;
    const int wm = wid&3, wn = wid>>2;
    const size_t bh = blockIdx.y;
    const int m0 = blockIdx.x*128;
    const float* ap = attn + (bh*S_+m0)*(size_t)S_;
    const float* vp = v + bh*(size_t)S_*D_;

    load_stageB(smemB, ap, vp, 0, tid);
    CP_COMMIT();

    float acc[2][8][4] = {};
    #pragma unroll 1
    for (int ks=0; ks<64; ++ks){
        CP_WAIT0();
        __syncthreads();
        if (ks<63){
            load_stageB(smemB + ((ks+1)&1)*B_STAGE, ap, vp, ks+1, tid);
            CP_COMMIT();
        }
        const float* sa = smemB + (ks&1)*B_STAGE;
        const float* sb = sa + SA_FLOATS;
        const float* ar = sa + (wm*32+g)*PA + ctg;
        #pragma unroll
        for (int k8=0; k8<4; ++k8){
            unsigned a00 = f2tf(ar[k8*8        ]);
            unsigned a01 = f2tf(ar[k8*8 +  8*PA]);
            unsigned a02 = f2tf(ar[k8*8 + 4      ]);
            unsigned a03 = f2tf(ar[k8*8 + 4 + 8*PA]);
            unsigned a10 = f2tf(ar[k8*8 + 16*PA]);
            unsigned a11 = f2tf(ar[k8*8 + 24*PA]);
            unsigned a12 = f2tf(ar[k8*8 + 4 + 16*PA]);
            unsigned a13 = f2tf(ar[k8*8 + 4 + 24*PA]);
            const float* vr  = sb + (k8*8+ctg)*PB + wn*64 + g;
            const float* vr4 = vr + 4*PB;
            #pragma unroll
            for (int j=0;j<8;++j){
                unsigned b0 = f2tf(vr[j*8]);
                unsigned b1 = f2tf(vr4[j*8]);
                mma_tf32(acc[0][j], a00,a01,a02,a03, b0,b1);
                mma_tf32(acc[1][j], a10,a11,a12,a13, b0,b1);
            }
        }
    }

    #pragma unroll
    for (int mi=0; mi<2; ++mi){
        float* opL = out + (bh*S_ + m0 + wm*32 + mi*16 + g    )*(size_t)D_ + wn*64 + 2*ctg;
        float* opH = out + (bh*S_ + m0 + wm*32 + mi*16 + g + 8)*(size_t)D_ + wn*64 + 2*ctg;
        #pragma unroll
        for (int j=0;j<8;++j){
            *(float2*)(opL + j*8) = make_float2(acc[mi][j][0], acc[mi][j][1]);
            *(float2*)(opH + j*8) = make_float2(acc[mi][j][2], acc[mi][j][3]);
        }
    }
}

extern "C" void kernel_launch(void* const* d_in, const int* in_sizes, int n_in,
                              void* d_out, int out_size)
{
    const float* q    = (const float*)d_in[0];
    const float* k    = (const float*)d_in[1];
    const float* v    = (const float*)d_in[2];
    const int*   mask = (const int*)  d_in[3];
    const float* bias = (const float*)d_in[4];
    float* out  = (float*)d_out;
    float* attn = out + (size_t)B_*H_*S_*D_;   // tuple output: (out, attn)

    cudaFuncSetAttribute(scores_kernel,
                         cudaFuncAttributeMaxDynamicSharedMemorySize, A_SMEM_BYTES);
    cudaFuncSetAttribute(pv_kernel,
                         cudaFuncAttributeMaxDynamicSharedMemorySize, B_SMEM_BYTES);

    dim3 gA(S_/MQ, 2*H_);     // x = q-tile (K reuse), y = (h,b) pairs (bias reuse)
    scores_kernel<<<gA, 512, A_SMEM_BYTES>>>(q, k, mask, bias, attn);

    dim3 gB(S_/128, B_*H_);
    pv_kernel<<<gB, 256, B_SMEM_BYTES>>>(attn, v, out);
}

// round 14
// speedup vs baseline: 2.5482x; 1.0162x over previous
#include <cuda_runtime.h>
#include <cstdint>
#include <cstddef>

#define B_ 2
#define H_ 16
#define S_ 2048
#define D_ 128
#define SCALE_L2E 0.12751744912f     // (1/sqrt(128)) * log2(e)
#define L2E       1.4426950408889634f

__device__ float g_inv[B_*H_*S_];    // per-row 1/rowsum scratch (256 KB)

__device__ __forceinline__ unsigned f2tf(float x){
    unsigned u; asm("cvt.rna.tf32.f32 %0, %1;" : "=r"(u) : "f"(x)); return u;
}
__device__ __forceinline__ void mma_tf32(float* c,
    unsigned a0,unsigned a1,unsigned a2,unsigned a3, unsigned b0, unsigned b1){
    asm volatile("mma.sync.aligned.m16n8k8.row.col.f32.tf32.tf32.f32 "
        "{%0,%1,%2,%3}, {%4,%5,%6,%7}, {%8,%9}, {%0,%1,%2,%3};"
        : "+f"(c[0]),"+f"(c[1]),"+f"(c[2]),"+f"(c[3])
        : "r"(a0),"r"(a1),"r"(a2),"r"(a3),"r"(b0),"r"(b1));
}
__device__ __forceinline__ void cpa16(float* dst, const float* src){
    unsigned d = (unsigned)__cvta_generic_to_shared(dst);
    asm volatile("cp.async.cg.shared.global [%0], [%1], 16;" :: "r"(d), "l"(src));
}
#define CP_COMMIT() asm volatile("cp.async.commit_group;")
#define CP_WAIT0()  asm volatile("cp.async.wait_group 0;")

// exp2 on the FMA pipe; clamped at -126; ~4e-5 rel err
__device__ __forceinline__ float exp2_fast(float t){
    t = fmaxf(t, -126.0f);
    float r = t + 12582912.0f;
    float f = t - (r - 12582912.0f);
    float p = 0.009618129f;
    p = fmaf(p, f, 0.055504109f);
    p = fmaf(p, f, 0.240226507f);
    p = fmaf(p, f, 0.693147181f);
    p = fmaf(p, f, 1.0f);
    return __uint_as_float(__float_as_uint(p) + (__float_as_uint(r) << 23));
}

// ===================== Kernel A: e = exp2(masked scores) + row-sum inverses =====================
#define MQ 64
#define KC 64
#define NC (S_/KC)                       // 32
#define PQ 132
#define PK 132
#define QS_FLOATS (MQ*PQ)                // 8448
#define KT_FLOATS (KC*PK)                // 8448
#define A_SMEM_FLOATS (QS_FLOATS + 2*KT_FLOATS + 384)
#define A_SMEM_BYTES  (A_SMEM_FLOATS*4)  // 102912

__device__ __forceinline__ void load_kchunk(float* dst, const float* src, int tid){
    #pragma unroll
    for (int i=0;i<4;i++){
        int c = tid + i*512;
        int row = c>>5, seg = c&31;
        cpa16(dst + row*PK + seg*4, src + (size_t)row*D_ + seg*4);
    }
}

__global__ __launch_bounds__(512,2)
void scores_kernel(const float* __restrict__ q, const float* __restrict__ k,
                   const int* __restrict__ mask, const float* __restrict__ bias,
                   float* __restrict__ attn)
{
    extern __shared__ float smem[];
    float* qs   = smem;
    float* kbuf = smem + QS_FLOATS;
    float* red  = smem + QS_FLOATS + 2*KT_FLOATS;

    const int tid = threadIdx.x, warp = tid>>5, lane = tid&31;
    const int g = lane>>2, ctg = lane&3;
    const int wm = warp&3, wn = warp>>2;
    const int h = blockIdx.y>>1, b = blockIdx.y&1;
    const size_t bh = (size_t)(b*H_+h);
    const int m0 = blockIdx.x*MQ;
    const float* qp = q + (bh*S_+m0)*(size_t)D_;
    const float* kp = k + bh*(size_t)S_*D_;
    float* attn_base = attn + (bh*S_+m0)*(size_t)S_;

    // ---- stage Q as permuted tf32: within 8-group, col c -> (c&3)*2 + (c>>2) ----
    {
        int row = tid>>3, seg = tid&7;
        #pragma unroll
        for (int gi=0; gi<2; ++gi){
            int c0 = seg*16 + gi*8;
            const float* s = qp + (size_t)row*D_ + c0;
            float4 t0 = *(const float4*)(s);
            float4 t1 = *(const float4*)(s+4);
            unsigned* d = (unsigned*)(qs + row*PQ + c0);
            d[0]=f2tf(t0.x); d[2]=f2tf(t0.y); d[4]=f2tf(t0.z); d[6]=f2tf(t0.w);
            d[1]=f2tf(t1.x); d[3]=f2tf(t1.y); d[5]=f2tf(t1.z); d[7]=f2tf(t1.w);
        }
    }
    load_kchunk(kbuf, kp, tid);
    CP_COMMIT();
    __syncthreads();

    float sums[2] = {0.f,0.f};

    #pragma unroll 1
    for (int nc=0; nc<NC; ++nc){
        CP_WAIT0();
        __syncthreads();
        if (nc<NC-1){
            load_kchunk(kbuf + ((nc+1)&1)*KT_FLOATS, kp + (size_t)(nc+1)*KC*D_, tid);
            CP_COMMIT();
        }
        const float* kb = kbuf + (nc&1)*KT_FLOATS;
        float acc[2][4] = {};
        const unsigned* qa = (const unsigned*)(qs + (wm*16+g)*PQ) + 2*ctg;
        const float* kr = kb + (wn*16+g)*PK + ctg;
        #pragma unroll
        for (int k8=0; k8<16; ++k8){
            uint2 aL = *(const uint2*)(qa + k8*8);
            uint2 aH = *(const uint2*)(qa + 8*PQ + k8*8);
            #pragma unroll
            for (int j=0;j<2;++j){
                unsigned b0 = f2tf(kr[j*8*PK + k8*8]);
                unsigned b1 = f2tf(kr[j*8*PK + k8*8 + 4]);
                mma_tf32(acc[j], aL.x,aH.x,aL.y,aH.y, b0,b1);
            }
        }
        const int ncol = nc*KC + wn*16 + 2*ctg;
        #pragma unroll
        for (int hi=0; hi<2; ++hi){
            int r = wm*16 + hi*8 + g;
            const float* bp = bias + ((size_t)h*S_ + m0 + r)*S_ + ncol;
            const int*   mp = mask + ((size_t)b*S_ + m0 + r)*S_ + ncol;
            float* ap = attn_base + (size_t)r*S_ + ncol;
            float s = 0.f;
            #pragma unroll
            for (int j=0;j<2;++j){
                float2 bb = *(const float2*)(bp + j*8);
                int2   mm = *(const int2*)(mp + j*8);
                float c0 = acc[j][hi*2], c1 = acc[j][hi*2+1];
                float x0 = mm.x ? fmaf(bb.x, L2E, c0*SCALE_L2E) : -126.0f;
                float x1 = mm.y ? fmaf(bb.y, L2E, c1*SCALE_L2E) : -126.0f;
                float e0 = exp2_fast(x0), e1 = exp2_fast(x1);
                *(float2*)(ap + j*8) = make_float2(e0,e1);
                s += e0+e1;
            }
            sums[hi] += s;
        }
    }

    // ---- row-sum reduce -> g_inv ----
    #pragma unroll
    for (int i=0;i<2;++i){
        sums[i] += __shfl_xor_sync(~0u, sums[i], 1);
        sums[i] += __shfl_xor_sync(~0u, sums[i], 2);
    }
    if (ctg==0){
        red[wn*64 + wm*16 +     g] = sums[0];
        red[wn*64 + wm*16 + 8 + g] = sums[1];
    }
    __syncthreads();
    if (tid < 64){
        float s = red[tid] + red[64+tid] + red[128+tid] + red[192+tid];
        g_inv[bh*S_ + m0 + tid] = 1.0f/s;
    }
}

// ===================== Kernel B: out = (e*inv) @ V, and write normalized attn =====================
#define PA 36
#define PB 136
#define SA_FLOATS (128*PA)               // 4608
#define SB_FLOATS (32*PB)                // 4352
#define B_STAGE   (SA_FLOATS + SB_FLOATS)
#define B_SMEM_BYTES ((2*B_STAGE + 128)*4)   // 72192

__device__ __forceinline__ void load_stageB(float* sa, const float* ap, const float* vp,
                                            int ks, int tid){
    float* sb = sa + SA_FLOATS;
    #pragma unroll
    for (int i=0;i<4;++i){
        int c = tid + i*256;
        int row = c>>3, c16 = c&7;
        cpa16(sa + row*PA + c16*4, ap + (size_t)row*S_ + ks*32 + c16*4);
    }
    #pragma unroll
    for (int i=0;i<4;++i){
        int c = tid + i*256;
        int row = c>>5, c32 = c&31;
        cpa16(sb + row*PB + c32*4, vp + (size_t)(ks*32+row)*D_ + c32*4);
    }
}

__global__ __launch_bounds__(256,2)
void pv_kernel(float* attn, const float* __restrict__ v, float* __restrict__ out)
{
    extern __shared__ float smemB[];
    float* sinv = smemB + 2*B_STAGE;
    const int tid = threadIdx.x, wid = tid>>5, lane = tid&31;
    const int g = lane>>2, ctg = lane&3;
    const int wm = wid&3, wn = wid>>2;
    const size_t bh = blockIdx.y;
    const int m0 = blockIdx.x*128;
    float* ap = attn + (bh*S_+m0)*(size_t)S_;
    const float* vp = v + bh*(size_t)S_*D_;

    // row inverses: fragment copies (regs) + writeback copies (smem)
    const float* ivp = g_inv + bh*S_ + m0;
    float iv0 = __ldg(ivp + wm*32 + g);
    float iv1 = __ldg(ivp + wm*32 + g + 8);
    float iv2 = __ldg(ivp + wm*32 + g + 16);
    float iv3 = __ldg(ivp + wm*32 + g + 24);
    if (tid < 128) sinv[tid] = __ldg(ivp + tid);

    load_stageB(smemB, ap, vp, 0, tid);
    CP_COMMIT();

    float acc[2][8][4] = {};
    #pragma unroll 1
    for (int ks=0; ks<64; ++ks){
        CP_WAIT0();
        __syncthreads();
        if (ks<63){
            load_stageB(smemB + ((ks+1)&1)*B_STAGE, ap, vp, ks+1, tid);
            CP_COMMIT();
        }
        float* sa = smemB + (ks&1)*B_STAGE;
        const float* sb = sa + SA_FLOATS;

        // ---- write normalized attn for this k-chunk (e*inv), coalesced 128B rows ----
        #pragma unroll
        for (int i=0;i<4;++i){
            int c = tid + i*256;
            int row = c>>3, seg = c&7;
            float4 e4 = *(const float4*)(sa + row*PA + seg*4);
            float inv = sinv[row];
            e4.x*=inv; e4.y*=inv; e4.z*=inv; e4.w*=inv;
            *(float4*)(ap + (size_t)row*S_ + ks*32 + seg*4) = e4;
        }

        const float* ar = sa + (wm*32+g)*PA + ctg;
        #pragma unroll
        for (int k8=0; k8<4; ++k8){
            unsigned a00 = f2tf(ar[k8*8        ]*iv0);
            unsigned a01 = f2tf(ar[k8*8 +  8*PA]*iv1);
            unsigned a02 = f2tf(ar[k8*8 + 4      ]*iv0);
            unsigned a03 = f2tf(ar[k8*8 + 4 + 8*PA]*iv1);
            unsigned a10 = f2tf(ar[k8*8 + 16*PA]*iv2);
            unsigned a11 = f2tf(ar[k8*8 + 24*PA]*iv3);
            unsigned a12 = f2tf(ar[k8*8 + 4 + 16*PA]*iv2);
            unsigned a13 = f2tf(ar[k8*8 + 4 + 24*PA]*iv3);
            const float* vr  = sb + (k8*8+ctg)*PB + wn*64 + g;
            const float* vr4 = vr + 4*PB;
            #pragma unroll
            for (int j=0;j<8;++j){
                unsigned b0 = f2tf(vr[j*8]);
                unsigned b1 = f2tf(vr4[j*8]);
                mma_tf32(acc[0][j], a00,a01,a02,a03, b0,b1);
                mma_tf32(acc[1][j], a10,a11,a12,a13, b0,b1);
            }
        }
    }

    #pragma unroll
    for (int mi=0; mi<2; ++mi){
        float* opL = out + (bh*S_ + m0 + wm*32 + mi*16 + g    )*(size_t)D_ + wn*64 + 2*ctg;
        float* opH = out + (bh*S_ + m0 + wm*32 + mi*16 + g + 8)*(size_t)D_ + wn*64 + 2*ctg;
        #pragma unroll
        for (int j=0;j<8;++j){
            *(float2*)(opL + j*8) = make_float2(acc[mi][j][0], acc[mi][j][1]);
            *(float2*)(opH + j*8) = make_float2(acc[mi][j][2], acc[mi][j][3]);
        }
    }
}

extern "C" void kernel_launch(void* const* d_in, const int* in_sizes, int n_in,
                              void* d_out, int out_size)
{
    const float* q    = (const float*)d_in[0];
    const float* k    = (const float*)d_in[1];
    const float* v    = (const float*)d_in[2];
    const int*   mask = (const int*)  d_in[3];
    const float* bias = (const float*)d_in[4];
    float* out  = (float*)d_out;
    float* attn = out + (size_t)B_*H_*S_*D_;   // tuple output: (out, attn)

    cudaFuncSetAttribute(scores_kernel,
                         cudaFuncAttributeMaxDynamicSharedMemorySize, A_SMEM_BYTES);
    cudaFuncSetAttribute(pv_kernel,
                         cudaFuncAttributeMaxDynamicSharedMemorySize, B_SMEM_BYTES);

    dim3 gA(S_/MQ, 2*H_);
    scores_kernel<<<gA, 512, A_SMEM_BYTES>>>(q, k, mask, bias, attn);

    dim3 gB(S_/128, B_*H_);
    pv_kernel<<<gB, 256, B_SMEM_BYTES>>>(attn, v, out);
}